// round 17
// baseline (speedup 1.0000x reference)
#include <cuda_runtime.h>
#include <math.h>

#define NPTS   500000
#define MCLUS  50000
#define NTILE_ATT ((NPTS + 127) / 128)    // 3907
#define NTILE_M   ((MCLUS + 127) / 128)   // 391

__device__ float g_agg[(size_t)MCLUS * 132];   // 131 used + 1 pad
__device__ float g_h[(size_t)MCLUS * 128];

// ---------------- helpers ----------------
__device__ __forceinline__ void red4(float* addr, float a, float b, float c, float d) {
    asm volatile("red.global.add.v4.f32 [%0], {%1,%2,%3,%4};"
                 :: "l"(addr), "f"(a), "f"(b), "f"(c), "f"(d) : "memory");
}
__device__ __forceinline__ void cpasync16(void* smem_dst, const void* gsrc) {
    unsigned saddr = (unsigned)__cvta_generic_to_shared(smem_dst);
    asm volatile("cp.async.cg.shared.global [%0], [%1], 16;" :: "r"(saddr), "l"(gsrc));
}
__device__ __forceinline__ void cp_commit() { asm volatile("cp.async.commit_group;"); }
__device__ __forceinline__ void cp_wait0() { asm volatile("cp.async.wait_group 0;" ::: "memory"); }
__device__ __forceinline__ void cp_wait1() { asm volatile("cp.async.wait_group 1;" ::: "memory"); }

__device__ __forceinline__ unsigned cvt_tf32(float f) {
    unsigned x;
    asm("cvt.rna.tf32.f32 %0, %1;" : "=r"(x) : "f"(f));
    return x;
}
__device__ __forceinline__ void mma_tf32(float* c, unsigned a0, unsigned a1,
                                         unsigned a2, unsigned a3,
                                         unsigned b0, unsigned b1) {
    asm volatile(
        "mma.sync.aligned.m16n8k8.row.col.f32.tf32.tf32.f32 "
        "{%0,%1,%2,%3}, {%4,%5,%6,%7}, {%8,%9}, {%0,%1,%2,%3};"
        : "+f"(c[0]), "+f"(c[1]), "+f"(c[2]), "+f"(c[3])
        : "r"(a0), "r"(a1), "r"(a2), "r"(a3), "r"(b0), "r"(b1));
}

#define SA 136   // A-tile row stride (floats): conflict-free
#define SB 72    // B-tile row stride (tf32 words): conflict-free

// ---------------- kernel 0: zero agg ----------------
__global__ void zero_agg_kernel() {
    const size_t total4 = (size_t)MCLUS * 132 / 4;
    float4* p = (float4*)g_agg;
    float4 z = make_float4(0.f, 0.f, 0.f, 0.f);
    for (size_t i = blockIdx.x * blockDim.x + threadIdx.x; i < total4;
         i += (size_t)gridDim.x * blockDim.x)
        p[i] = z;
}

// ============ kernel 1: attention MLP (tf32 MMA) + scatter ============
// Persistent, per-warp pipelines with TILE-LEVEL DOUBLE BUFFERING:
// while computing/scattering tile n from buf p, tile n+1 streams into buf p^1.
// 1 CTA/SM (grid 148), 8 warps, warp w owns tile rows w*16..w*16+15.
__global__ void __launch_bounds__(256, 1) att_scatter_kernel(
    const float* __restrict__ feat, const float* __restrict__ pts,
    const float* __restrict__ ctr, const int* __restrict__ lab,
    const float* __restrict__ aW1, const float* __restrict__ ab1,
    const float* __restrict__ aW2, const float* __restrict__ ab2)
{
    extern __shared__ char dynRaw[];
    float*    sAb[2];
    sAb[0] = (float*)dynRaw;                              // 128*SA
    sAb[1] = sAb[0] + 128 * SA;                           // 128*SA
    unsigned* sWb = (unsigned*)(sAb[1] + 128 * SA);       // 136*SB
    float*    sB1 = (float*)(sWb + 136 * SB);             // 64
    float*    sA2 = sB1 + 64;                             // 64
    float*    sAtt = sA2 + 64;                            // 128
    int*      sLab = (int*)(sAtt + 128);                  // 2*128
    float*    sb2p = (float*)(sLab + 256);

    const int tid = threadIdx.x;
    const float4* f4 = (const float4*)feat;

    for (int idx = tid; idx < 136 * 64; idx += 256) {
        int k = idx >> 6, n = idx & 63;
        float v = (k < 131) ? aW1[k * 64 + n] : 0.f;
        sWb[k * SB + n] = cvt_tf32(v);
    }
    if (tid < 64) { sB1[tid] = ab1[tid]; sA2[tid] = aW2[tid]; }
    if (tid == 0) *sb2p = ab2[0];
    __syncthreads();

    const int w = tid >> 5;
    const int lane = tid & 31;
    const int g = lane >> 2;
    const int t = lane & 3;
    const int rbase = w * 16;
    const float b2v = *sb2p;

    int tile = blockIdx.x;
    if (tile >= NTILE_ATT) return;

    // ---- preamble: stage tile0 into buf0 (cp.async + labels/rel) ----
    {
        const int gbase = tile * 128;
        for (int idx = lane; idx < 16 * 32; idx += 32) {
            int r = idx >> 5, c4 = idx & 31;
            int gr = gbase + rbase + r; if (gr >= NPTS) gr = NPTS - 1;
            cpasync16(sAb[0] + (rbase + r) * SA + c4 * 4, f4 + (size_t)gr * 32 + c4);
        }
        cp_commit();
        if (lane < 16) {
            int rl = rbase + lane;
            int row = gbase + rl;
            int rc = (row < NPTS) ? row : (NPTS - 1);
            int l = lab[rc];
            sLab[rl] = l;
            float* Ar = sAb[0] + rl * SA;
            Ar[128] = ctr[l * 3 + 0] - pts[rc * 3 + 0];
            Ar[129] = ctr[l * 3 + 1] - pts[rc * 3 + 1];
            Ar[130] = ctr[l * 3 + 2] - pts[rc * 3 + 2];
            Ar[131] = 0.f; Ar[132] = 0.f; Ar[133] = 0.f; Ar[134] = 0.f; Ar[135] = 0.f;
        }
    }

    int p = 0;
    for (; tile < NTILE_ATT; tile += gridDim.x, p ^= 1) {
        const int gbase = tile * 128;
        const int next = tile + gridDim.x;
        const bool hasNext = (next < NTILE_ATT);

        // issue next tile's cp.async into the other buffer, prefetch its labels/rel
        int   nl = 0;
        float nrx = 0.f, nry = 0.f, nrz = 0.f;
        if (hasNext) {
            const int nbase = next * 128;
            float* dst = sAb[p ^ 1];
            for (int idx = lane; idx < 16 * 32; idx += 32) {
                int r = idx >> 5, c4 = idx & 31;
                int gr = nbase + rbase + r; if (gr >= NPTS) gr = NPTS - 1;
                cpasync16(dst + (rbase + r) * SA + c4 * 4, f4 + (size_t)gr * 32 + c4);
            }
            cp_commit();
            if (lane < 16) {
                int row = nbase + rbase + lane;
                int rc = (row < NPTS) ? row : (NPTS - 1);
                nl = lab[rc];
                nrx = ctr[nl * 3 + 0] - pts[rc * 3 + 0];
                nry = ctr[nl * 3 + 1] - pts[rc * 3 + 1];
                nrz = ctr[nl * 3 + 2] - pts[rc * 3 + 2];
            }
            cp_wait1();   // wait only the OLDER group (current tile)
        } else {
            cp_wait0();
        }
        __syncwarp();

        const float* sA = sAb[p];

        float acc[8][4];
#pragma unroll
        for (int nf = 0; nf < 8; nf++) {
            acc[nf][0] = 0.f; acc[nf][1] = 0.f; acc[nf][2] = 0.f; acc[nf][3] = 0.f;
        }

        const float* Ar0 = sA + (rbase + g) * SA;
        const float* Ar1 = Ar0 + 8 * SA;

#pragma unroll 1
        for (int kf = 0; kf < 17; kf++) {
            int k0 = kf * 8;
            unsigned a0 = cvt_tf32(Ar0[k0 + t]);
            unsigned a1 = cvt_tf32(Ar1[k0 + t]);
            unsigned a2 = cvt_tf32(Ar0[k0 + t + 4]);
            unsigned a3 = cvt_tf32(Ar1[k0 + t + 4]);
            const unsigned* B0 = sWb + (k0 + t) * SB + g;
            const unsigned* B1 = sWb + (k0 + t + 4) * SB + g;
#pragma unroll
            for (int nf = 0; nf < 8; nf++) {
                mma_tf32(acc[nf], a0, a1, a2, a3, B0[nf * 8], B1[nf * 8]);
            }
        }

        // write next tile's labels/rel (into the buffer being filled; cols 128+
        // are untouched by cp.async so no conflict with in-flight group)
        if (hasNext && lane < 16) {
            int rl = rbase + lane;
            sLab[(p ^ 1) * 128 + rl] = nl;
            float* Ar = sAb[p ^ 1] + rl * SA;
            Ar[128] = nrx; Ar[129] = nry; Ar[130] = nrz;
            Ar[131] = 0.f; Ar[132] = 0.f; Ar[133] = 0.f; Ar[134] = 0.f; Ar[135] = 0.f;
        }

        // epilogue: bias+relu -> dot aW2 -> reduce over t -> sigmoid -> sAtt
        {
            float s0 = 0.f, s1 = 0.f;
#pragma unroll
            for (int nf = 0; nf < 8; nf++) {
                int c0 = nf * 8 + 2 * t, c1 = c0 + 1;
                float bb0 = sB1[c0], bb1 = sB1[c1];
                float w0 = sA2[c0], w1 = sA2[c1];
                s0 += fmaxf(acc[nf][0] + bb0, 0.f) * w0 + fmaxf(acc[nf][1] + bb1, 0.f) * w1;
                s1 += fmaxf(acc[nf][2] + bb0, 0.f) * w0 + fmaxf(acc[nf][3] + bb1, 0.f) * w1;
            }
            s0 += __shfl_xor_sync(0xffffffffu, s0, 1);
            s0 += __shfl_xor_sync(0xffffffffu, s0, 2);
            s1 += __shfl_xor_sync(0xffffffffu, s1, 1);
            s1 += __shfl_xor_sync(0xffffffffu, s1, 2);
            if (t == 0) {
                sAtt[rbase + g]     = 1.f / (1.f + expf(-(s0 + b2v)));
                sAtt[rbase + g + 8] = 1.f / (1.f + expf(-(s1 + b2v)));
            }
        }
        __syncwarp();

        // scatter from current buffer
        for (int idx = lane; idx < 16 * 33; idx += 32) {
            int r = idx / 33, c = idx - r * 33;
            int rl = rbase + r;
            int grow = gbase + rl;
            if (grow < NPTS) {
                float a = sAtt[rl];
                int l = sLab[p * 128 + rl];
                float4 v = *(const float4*)(sA + rl * SA + c * 4);
                red4(g_agg + (size_t)l * 132 + c * 4,
                     v.x * a, v.y * a, v.z * a, v.w * a);
            }
        }
        __syncwarp();
    }
}

// ============ kernel 2: h = relu(agg @ oW1 + ob1)  (tf32 MMA) ============
// grid (148, 2): y = 64-col slice; persistent, per-warp pipelines
__global__ void __launch_bounds__(256, 2) gemmB_kernel(
    const float* __restrict__ oW1, const float* __restrict__ ob1)
{
    extern __shared__ char dynRaw[];
    float*    sA  = (float*)dynRaw;                       // 128*SA
    unsigned* sWb = (unsigned*)(dynRaw + 128 * SA * 4);   // 136*SB

    const int tid = threadIdx.x;
    const int slice = blockIdx.y;
    const float4* a4 = (const float4*)g_agg;   // 33 f4/row

    for (int idx = tid; idx < 136 * 64; idx += 256) {
        int k = idx >> 6, n = idx & 63;
        float v = (k < 131) ? oW1[k * 128 + slice * 64 + n] : 0.f;
        sWb[k * SB + n] = cvt_tf32(v);
    }
    __syncthreads();

    const int w = tid >> 5;
    const int lane = tid & 31;
    const int g = lane >> 2;
    const int t = lane & 3;
    const int rbase = w * 16;

    float bias0[8], bias1[8];
#pragma unroll
    for (int nf = 0; nf < 8; nf++) {
        int c0 = slice * 64 + nf * 8 + 2 * t;
        bias0[nf] = __ldg(ob1 + c0);
        bias1[nf] = __ldg(ob1 + c0 + 1);
    }

    for (int tile = blockIdx.x; tile < NTILE_M; tile += gridDim.x) {
        const int gbase = tile * 128;

        for (int idx = lane; idx < 16 * 33; idx += 32) {
            int r = idx / 33, c4 = idx - r * 33;
            int gr = gbase + rbase + r; if (gr >= MCLUS) gr = MCLUS - 1;
            cpasync16(sA + (rbase + r) * SA + c4 * 4, a4 + (size_t)gr * 33 + c4);
        }
        cp_commit();
        if (lane < 16) {   // zero A cols 132..135
            float* Ar = sA + (rbase + lane) * SA;
            Ar[132] = 0.f; Ar[133] = 0.f; Ar[134] = 0.f; Ar[135] = 0.f;
        }
        cp_wait0();
        __syncwarp();

        float acc[8][4];
#pragma unroll
        for (int nf = 0; nf < 8; nf++) {
            acc[nf][0] = 0.f; acc[nf][1] = 0.f; acc[nf][2] = 0.f; acc[nf][3] = 0.f;
        }

        const float* Ar0 = sA + (rbase + g) * SA;
        const float* Ar1 = Ar0 + 8 * SA;

#pragma unroll 1
        for (int kf = 0; kf < 17; kf++) {
            int k0 = kf * 8;
            unsigned a0 = cvt_tf32(Ar0[k0 + t]);
            unsigned a1 = cvt_tf32(Ar1[k0 + t]);
            unsigned a2 = cvt_tf32(Ar0[k0 + t + 4]);
            unsigned a3 = cvt_tf32(Ar1[k0 + t + 4]);
            const unsigned* B0 = sWb + (k0 + t) * SB + g;
            const unsigned* B1 = sWb + (k0 + t + 4) * SB + g;
#pragma unroll
            for (int nf = 0; nf < 8; nf++) {
                mma_tf32(acc[nf], a0, a1, a2, a3, B0[nf * 8], B1[nf * 8]);
            }
        }

        int r0 = gbase + rbase + g;
        int r1 = r0 + 8;
#pragma unroll
        for (int nf = 0; nf < 8; nf++) {
            int c0 = slice * 64 + nf * 8 + 2 * t;
            if (r0 < MCLUS)
                *(float2*)(g_h + (size_t)r0 * 128 + c0) =
                    make_float2(fmaxf(acc[nf][0] + bias0[nf], 0.f),
                                fmaxf(acc[nf][1] + bias1[nf], 0.f));
            if (r1 < MCLUS)
                *(float2*)(g_h + (size_t)r1 * 128 + c0) =
                    make_float2(fmaxf(acc[nf][2] + bias0[nf], 0.f),
                                fmaxf(acc[nf][3] + bias1[nf], 0.f));
        }
        __syncwarp();
    }
}

// ============ kernel 3: out = relu(h @ oW2 + ob2)  (tf32 MMA) ============
// grid (74, 4): y = 64-col slice; persistent, per-warp pipelines
__global__ void __launch_bounds__(256, 2) gemmC_kernel(
    const float* __restrict__ oW2, const float* __restrict__ ob2,
    float* __restrict__ out)
{
    extern __shared__ char dynRaw[];
    float*    sA  = (float*)dynRaw;                       // 128*SA
    unsigned* sWb = (unsigned*)(dynRaw + 128 * SA * 4);   // 128*SB

    const int tid = threadIdx.x;
    const int slice = blockIdx.y;
    const float4* h4 = (const float4*)g_h;   // 32 f4/row

    for (int idx = tid; idx < 128 * 64; idx += 256) {
        int k = idx >> 6, n = idx & 63;
        sWb[k * SB + n] = cvt_tf32(oW2[k * 256 + slice * 64 + n]);
    }
    __syncthreads();

    const int w = tid >> 5;
    const int lane = tid & 31;
    const int g = lane >> 2;
    const int t = lane & 3;
    const int rbase = w * 16;

    float bias0[8], bias1[8];
#pragma unroll
    for (int nf = 0; nf < 8; nf++) {
        int c0 = slice * 64 + nf * 8 + 2 * t;
        bias0[nf] = __ldg(ob2 + c0);
        bias1[nf] = __ldg(ob2 + c0 + 1);
    }

    for (int tile = blockIdx.x; tile < NTILE_M; tile += gridDim.x) {
        const int gbase = tile * 128;

        for (int idx = lane; idx < 16 * 32; idx += 32) {
            int r = idx >> 5, c4 = idx & 31;
            int gr = gbase + rbase + r; if (gr >= MCLUS) gr = MCLUS - 1;
            cpasync16(sA + (rbase + r) * SA + c4 * 4, h4 + (size_t)gr * 32 + c4);
        }
        cp_commit();
        cp_wait0();
        __syncwarp();

        float acc[8][4];
#pragma unroll
        for (int nf = 0; nf < 8; nf++) {
            acc[nf][0] = 0.f; acc[nf][1] = 0.f; acc[nf][2] = 0.f; acc[nf][3] = 0.f;
        }

        const float* Ar0 = sA + (rbase + g) * SA;
        const float* Ar1 = Ar0 + 8 * SA;

#pragma unroll 1
        for (int kf = 0; kf < 16; kf++) {
            int k0 = kf * 8;
            unsigned a0 = cvt_tf32(Ar0[k0 + t]);
            unsigned a1 = cvt_tf32(Ar1[k0 + t]);
            unsigned a2 = cvt_tf32(Ar0[k0 + t + 4]);
            unsigned a3 = cvt_tf32(Ar1[k0 + t + 4]);
            const unsigned* B0 = sWb + (k0 + t) * SB + g;
            const unsigned* B1 = sWb + (k0 + t + 4) * SB + g;
#pragma unroll
            for (int nf = 0; nf < 8; nf++) {
                mma_tf32(acc[nf], a0, a1, a2, a3, B0[nf * 8], B1[nf * 8]);
            }
        }

        int r0 = gbase + rbase + g;
        int r1 = r0 + 8;
#pragma unroll
        for (int nf = 0; nf < 8; nf++) {
            int c0 = slice * 64 + nf * 8 + 2 * t;
            if (r0 < MCLUS)
                *(float2*)(out + (size_t)r0 * 256 + c0) =
                    make_float2(fmaxf(acc[nf][0] + bias0[nf], 0.f),
                                fmaxf(acc[nf][1] + bias1[nf], 0.f));
            if (r1 < MCLUS)
                *(float2*)(out + (size_t)r1 * 256 + c0) =
                    make_float2(fmaxf(acc[nf][2] + bias0[nf], 0.f),
                                fmaxf(acc[nf][3] + bias1[nf], 0.f));
        }
        __syncwarp();
    }
}

extern "C" void kernel_launch(void* const* d_in, const int* in_sizes, int n_in,
                              void* d_out, int out_size) {
    const float* feat = (const float*)d_in[0];
    const float* pts  = (const float*)d_in[1];
    const float* ctr  = (const float*)d_in[2];
    const int*   lab  = (const int*)d_in[3];
    const float* aW1  = (const float*)d_in[4];
    const float* ab1  = (const float*)d_in[5];
    const float* aW2  = (const float*)d_in[6];
    const float* ab2  = (const float*)d_in[7];
    const float* oW1  = (const float*)d_in[8];
    const float* ob1  = (const float*)d_in[9];
    const float* oW2  = (const float*)d_in[10];
    const float* ob2  = (const float*)d_in[11];
    float* out = (float*)d_out;

    const int attSmem = 2 * 128 * SA * 4 + 136 * SB * 4
                      + (64 + 64) * 4 + 128 * 4 + 256 * 4 + 16;
    const int bSmem   = 128 * SA * 4 + 136 * SB * 4;
    const int cSmem   = 128 * SA * 4 + 128 * SB * 4;

    static int inited = 0;
    if (!inited) {
        cudaFuncSetAttribute(att_scatter_kernel, cudaFuncAttributeMaxDynamicSharedMemorySize, attSmem);
        cudaFuncSetAttribute(gemmB_kernel, cudaFuncAttributeMaxDynamicSharedMemorySize, bSmem);
        cudaFuncSetAttribute(gemmC_kernel, cudaFuncAttributeMaxDynamicSharedMemorySize, cSmem);
        inited = 1;
    }

    zero_agg_kernel<<<2048, 256>>>();
    att_scatter_kernel<<<148, 256, attSmem>>>(feat, pts, ctr, lab,
                                              aW1, ab1, aW2, ab2);
    gemmB_kernel<<<dim3(148, 2), 256, bSmem>>>(oW1, ob1);
    gemmC_kernel<<<dim3(74, 4), 256, cSmem>>>(oW2, ob2, out);
}